// round 7
// baseline (speedup 1.0000x reference)
#include <cuda_runtime.h>
#include <math.h>

#define NPTS 2048
#define DIN  768
#define DOUT 64
#define NMAT 5
#define LN_N   7.624618986159398f      // ln(2048)
#define LOG2E  1.4426950408889634f
#define LN2    0.6931471805599453f

// ---------------------------------------------------------------------------
// Device scratch (static globals — no allocation in kernel_launch)
// ---------------------------------------------------------------------------
__device__ __align__(16) float d_Wt[DIN * DOUT];             // W^T: [768][64]
__device__ __align__(16) float d_P[3][NPTS * DOUT];          // pd, p1, p2
__device__ __align__(16) float d_SQ[3][NPTS];                // 0.5*||row||^2
__device__ __align__(16) float d_C[NMAT][(size_t)NPTS * NPTS];
// 0:Cxx 1:C11 2:C22 3:Cxy1 4:Cxy2
__device__ __align__(16) float d_pot[2][7][NPTS];            // ping-pong potentials
// slots: 0:f_xx 1:f_11 2:f_22 3:f_xy1 4:g_xy1 5:f_xy2 6:g_xy2
__device__ __align__(16) float d_potF[7][NPTS];              // final potentials

__constant__ int cAi[5] = {0, 1, 2, 0, 0};
__constant__ int cBi[5] = {0, 1, 2, 1, 2};

// pass -> (matrix, vin slot, out slot); passes 5,6 are column-mode
__constant__ int cMat[7] = {0, 1, 2, 3, 4, 3, 4};
__constant__ int cVin[7] = {0, 1, 2, 4, 6, 3, 5};
__constant__ int cOut[7] = {0, 1, 2, 3, 5, 4, 6};

__device__ __forceinline__ float ex2f(float x) {
    float r; asm("ex2.approx.ftz.f32 %0, %1;" : "=f"(r) : "f"(x)); return r;
}
__device__ __forceinline__ float lg2f(float x) {
    float r; asm("lg2.approx.f32 %0, %1;" : "=f"(r) : "f"(x)); return r;
}

// ---------------------------------------------------------------------------
// W transpose:  Wt[j][k] = W[k][j]
// ---------------------------------------------------------------------------
__global__ void k_transposeW(const float* __restrict__ W) {
    int e = blockIdx.x * blockDim.x + threadIdx.x;
    if (e < DIN * DOUT) {
        int j = e / DOUT, k = e % DOUT;
        d_Wt[e] = W[k * DIN + j];
    }
}

// ---------------------------------------------------------------------------
// predict: P = relu(X @ W^T + b). 64x64 tile / 256 threads.
// ---------------------------------------------------------------------------
__global__ __launch_bounds__(256) void k_predict(const float* __restrict__ X0,
                                                 const float* __restrict__ X1,
                                                 const float* __restrict__ X2,
                                                 const float* __restrict__ bias) {
    __shared__ __align__(16) float Xs[64 * 68];   // [kk][row]
    __shared__ __align__(16) float Ws[64 * 64];   // [kk][col]
    const float* X = (blockIdx.y == 0) ? X0 : (blockIdx.y == 1) ? X1 : X2;
    int rowBase = blockIdx.x * 64;
    int tid = threadIdx.x;
    int ty = tid >> 4, tx = tid & 15;

    float acc[4][4];
#pragma unroll
    for (int i = 0; i < 4; i++)
#pragma unroll
        for (int j = 0; j < 4; j++) acc[i][j] = 0.f;

    for (int k0 = 0; k0 < DIN; k0 += 64) {
#pragma unroll
        for (int i = 0; i < 16; i++) {
            int e = tid + i * 256;
            int r = e >> 6, c = e & 63;
            Xs[c * 68 + r] = X[(size_t)(rowBase + r) * DIN + k0 + c];
            Ws[r * 64 + c] = d_Wt[(k0 + r) * DOUT + c];
        }
        __syncthreads();
#pragma unroll
        for (int kk = 0; kk < 64; kk++) {
            float4 a = *reinterpret_cast<const float4*>(&Xs[kk * 68 + ty * 4]);
            float4 b = *reinterpret_cast<const float4*>(&Ws[kk * 64 + tx * 4]);
            float av[4] = {a.x, a.y, a.z, a.w};
            float bv[4] = {b.x, b.y, b.z, b.w};
#pragma unroll
            for (int i = 0; i < 4; i++)
#pragma unroll
                for (int j = 0; j < 4; j++) acc[i][j] = fmaf(av[i], bv[j], acc[i][j]);
        }
        __syncthreads();
    }

#pragma unroll
    for (int i = 0; i < 4; i++)
#pragma unroll
        for (int j = 0; j < 4; j++) {
            float v = acc[i][j] + bias[tx * 4 + j];
            v = fmaxf(v, 0.f);
            d_P[blockIdx.y][(rowBase + ty * 4 + i) * DOUT + tx * 4 + j] = v;
        }
}

// ---------------------------------------------------------------------------
// 0.5 * ||row||^2, one warp per row
// ---------------------------------------------------------------------------
__global__ void k_sqnorm() {
    int wid = threadIdx.x >> 5, lane = threadIdx.x & 31;
    int grow = blockIdx.x * 8 + wid;
    int b = grow >> 11, r = grow & (NPTS - 1);
    float v0 = d_P[b][r * DOUT + lane];
    float v1 = d_P[b][r * DOUT + 32 + lane];
    float v = v0 * v0 + v1 * v1;
#pragma unroll
    for (int off = 16; off > 0; off >>= 1)
        v += __shfl_xor_sync(0xffffffffu, v, off);
    if (lane == 0) d_SQ[b][r] = 0.5f * v;
}

// ---------------------------------------------------------------------------
// cost: C[i][j] = 0.5||a_i||^2 + 0.5||b_j||^2 - a_i . b_j  (K=64)
// 5 cost matrices in one launch (blockIdx.z). No transposes anymore.
// ---------------------------------------------------------------------------
__global__ __launch_bounds__(256) void k_cost() {
    __shared__ __align__(16) float sA[64 * 68];   // [kk][row]
    __shared__ __align__(16) float sB[64 * 68];   // [kk][col]
    const int z = blockIdx.z;
    const int ai = cAi[z], bi = cBi[z];
    const float* A = d_P[ai];
    const float* B = d_P[bi];
    int i0 = blockIdx.y * 64, j0 = blockIdx.x * 64;
    int tid = threadIdx.x, ty = tid >> 4, tx = tid & 15;

#pragma unroll
    for (int i = 0; i < 16; i++) {
        int e = tid + i * 256;
        int r = e >> 6, c = e & 63;
        sA[c * 68 + r] = A[(i0 + r) * DOUT + c];
        sB[c * 68 + r] = B[(j0 + r) * DOUT + c];
    }
    __syncthreads();

    float acc[4][4];
#pragma unroll
    for (int i = 0; i < 4; i++)
#pragma unroll
        for (int j = 0; j < 4; j++) acc[i][j] = 0.f;

#pragma unroll
    for (int kk = 0; kk < 64; kk++) {
        float4 a = *reinterpret_cast<const float4*>(&sA[kk * 68 + ty * 4]);
        float4 b = *reinterpret_cast<const float4*>(&sB[kk * 68 + tx * 4]);
        float av[4] = {a.x, a.y, a.z, a.w};
        float bv[4] = {b.x, b.y, b.z, b.w};
#pragma unroll
        for (int i = 0; i < 4; i++)
#pragma unroll
            for (int j = 0; j < 4; j++) acc[i][j] = fmaf(av[i], bv[j], acc[i][j]);
    }

    float sqa[4], sqb[4];
#pragma unroll
    for (int i = 0; i < 4; i++) sqa[i] = d_SQ[ai][i0 + ty * 4 + i];
#pragma unroll
    for (int j = 0; j < 4; j++) sqb[j] = d_SQ[bi][j0 + tx * 4 + j];

    float* Cm = d_C[z];
#pragma unroll
    for (int i = 0; i < 4; i++)
#pragma unroll
        for (int j = 0; j < 4; j++) {
            Cm[(size_t)(i0 + ty * 4 + i) * NPTS + j0 + tx * 4 + j] =
                sqa[i] + sqb[j] - acc[i][j];
        }
}

// ---------------------------------------------------------------------------
// zero ping-pong potential buffers
// ---------------------------------------------------------------------------
__global__ void k_init() {
    int e = blockIdx.x * blockDim.x + threadIdx.x;
    if (e < 2 * 7 * NPTS) (&d_pot[0][0][0])[e] = 0.f;
}

// ---------------------------------------------------------------------------
// One fused Sinkhorn scan step, 7 passes, 64 blocks each (grid = 448):
//   passes 0-4: row softmin (32 rows/block, 4 rows/warp, float4 loads)
//   passes 5-6: column softmin on row-major Cxy (32 cols/block, lane=col,
//               8 row-chunks of 256, online chunked LSE)
// f_i = eps*(ln N - ln2 * LSE2_j[(vin_j - C_ij)*log2e/eps])
// ---------------------------------------------------------------------------
__global__ __launch_bounds__(256, 4) void k_step(int cur, float eps, int avg, int fin) {
    __shared__ __align__(16) float sg[NPTS];
    __shared__ float smm[8][32];
    __shared__ float sms[8][32];

    const int nxt = cur ^ 1;
    const int pass = blockIdx.x >> 6;          // 0..6
    const int sub  = blockIdx.x & 63;
    const int vinSlot = cVin[pass];
    const int outSlot = cOut[pass];
    const float* __restrict__ vin  = d_pot[cur][vinSlot];
    const float* __restrict__ favg = d_pot[cur][outSlot];
    float* __restrict__ out = fin ? d_potF[outSlot] : d_pot[nxt][outSlot];
    const float* __restrict__ Cm = d_C[cMat[pass]];
    const float pscale = LOG2E / eps;
    const float nscale = -pscale;

    // stage vin * log2e/eps into shared
    {
        const float4* vin4 = reinterpret_cast<const float4*>(vin);
        float4* sg4s = reinterpret_cast<float4*>(sg);
        for (int j = threadIdx.x; j < NPTS / 4; j += 256) {
            float4 v = vin4[j];
            v.x *= pscale; v.y *= pscale; v.z *= pscale; v.w *= pscale;
            sg4s[j] = v;
        }
    }
    __syncthreads();

    const int wid = threadIdx.x >> 5, lane = threadIdx.x & 31;

    if (pass < 5) {
        // ---------------- row mode: 4 rows per warp ----------------
        const float4* sg4 = reinterpret_cast<const float4*>(sg);
#pragma unroll 1
        for (int r = 0; r < 4; r++) {
            const int row = sub * 32 + wid * 4 + r;
            const float4* __restrict__ Crow4 =
                reinterpret_cast<const float4*>(Cm + (size_t)row * NPTS);
            float m = -3.4e38f, s = 0.f;
#pragma unroll
            for (int c = 0; c < 4; c++) {
                float4 xv[4];
                float mc = -3.4e38f;
#pragma unroll
                for (int k = 0; k < 4; k++) {
                    float4 cc = Crow4[c * 128 + k * 32 + lane];
                    float4 gg = sg4[c * 128 + k * 32 + lane];
                    float4 t;
                    t.x = fmaf(cc.x, nscale, gg.x);
                    t.y = fmaf(cc.y, nscale, gg.y);
                    t.z = fmaf(cc.z, nscale, gg.z);
                    t.w = fmaf(cc.w, nscale, gg.w);
                    xv[k] = t;
                    mc = fmaxf(mc, fmaxf(fmaxf(t.x, t.y), fmaxf(t.z, t.w)));
                }
                float mn = fmaxf(m, mc);
                s = s * ex2f(m - mn);
#pragma unroll
                for (int k = 0; k < 4; k++) {
                    s += ex2f(xv[k].x - mn) + ex2f(xv[k].y - mn)
                       + ex2f(xv[k].z - mn) + ex2f(xv[k].w - mn);
                }
                m = mn;
            }
            // warp LSE combine
#pragma unroll
            for (int off = 16; off > 0; off >>= 1) {
                float mo = __shfl_xor_sync(0xffffffffu, m, off);
                float so = __shfl_xor_sync(0xffffffffu, s, off);
                float mn = fmaxf(m, mo);
                s = s * ex2f(m - mn) + so * ex2f(mo - mn);
                m = mn;
            }
            if (lane == 0) {
                float ft = eps * (LN_N - (m + lg2f(s)) * LN2);
                out[row] = avg ? 0.5f * (favg[row] + ft) : ft;
            }
        }
    } else {
        // ---------------- column mode: lane = column, warp = row chunk ----
        const int col = sub * 32 + lane;
        const float* __restrict__ Ccol = Cm + col;
        const int rowbase = wid * 256;
        float m = -3.4e38f, s = 0.f;
#pragma unroll 1
        for (int r0 = 0; r0 < 256; r0 += 8) {
            float t[8];
            float mc = -3.4e38f;
#pragma unroll
            for (int k = 0; k < 8; k++) {
                int rr = rowbase + r0 + k;
                float c = Ccol[(size_t)rr * NPTS];
                t[k] = fmaf(c, nscale, sg[rr]);
                mc = fmaxf(mc, t[k]);
            }
            float mn = fmaxf(m, mc);
            s = s * ex2f(m - mn);
#pragma unroll
            for (int k = 0; k < 8; k++) s += ex2f(t[k] - mn);
            m = mn;
        }
        smm[wid][lane] = m;
        sms[wid][lane] = s;
        __syncthreads();
        if (wid == 0) {
            float M = smm[0][lane], S = sms[0][lane];
#pragma unroll
            for (int w = 1; w < 8; w++) {
                float mo = smm[w][lane], so = sms[w][lane];
                float mn = fmaxf(M, mo);
                S = S * ex2f(M - mn) + so * ex2f(mo - mn);
                M = mn;
            }
            float gt = eps * (LN_N - (M + lg2f(S)) * LN2);
            out[col] = avg ? 0.5f * (favg[col] + gt) : gt;
        }
    }
}

// ---------------------------------------------------------------------------
// dist1 = <a, f_xy1 - f_xx> + <b, g_xy1 - g_y1y1>, dist2 analogous.
// out = sigmoid(10 * (dist2 - dist1))
// ---------------------------------------------------------------------------
__global__ void k_reduce(float* out) {
    __shared__ float s1h[256], s2h[256];
    int t = threadIdx.x;
    float a1 = 0.f, a2 = 0.f;
    for (int i = t; i < NPTS; i += 256) {
        float fxx = d_potF[0][i];
        a1 += (d_potF[3][i] - fxx) + (d_potF[4][i] - d_potF[1][i]);
        a2 += (d_potF[5][i] - fxx) + (d_potF[6][i] - d_potF[2][i]);
    }
    s1h[t] = a1;
    s2h[t] = a2;
    __syncthreads();
    for (int off = 128; off > 0; off >>= 1) {
        if (t < off) { s1h[t] += s1h[t + off]; s2h[t] += s2h[t + off]; }
        __syncthreads();
    }
    if (t == 0) {
        const float inv = 1.0f / (float)NPTS;
        float dist1 = s1h[0] * inv;
        float dist2 = s2h[0] * inv;
        float z = 10.0f * (dist2 - dist1);
        out[0] = 1.0f / (1.0f + expf(-z));
    }
}

// ---------------------------------------------------------------------------
// Launcher (graph-capturable: kernel launches only)
// ---------------------------------------------------------------------------
extern "C" void kernel_launch(void* const* d_in, const int* in_sizes, int n_in,
                              void* d_out, int out_size) {
    (void)in_sizes; (void)n_in; (void)out_size;
    const float* dX = (const float*)d_in[0];
    const float* s1 = (const float*)d_in[1];
    const float* s2 = (const float*)d_in[2];
    const float* W  = (const float*)d_in[3];
    const float* bb = (const float*)d_in[4];
    float* out = (float*)d_out;

    k_transposeW<<<(DIN * DOUT + 255) / 256, 256>>>(W);
    k_predict<<<dim3(NPTS / 64, 3), 256>>>(dX, s1, s2, bb);
    k_sqnorm<<<3 * NPTS / 8, 256>>>();
    k_cost<<<dim3(32, 32, 5), 256>>>();
    k_init<<<(2 * 7 * NPTS + 255) / 256, 256>>>();

    // epsilon schedule (geomloss-style), computed in double, cast to float
    const double eps0 = 32.0;
    const double epsf = pow(0.05, 2.0);
    const double ratio = pow(0.9, 2.0);
    int n = (int)ceil(log(epsf / eps0) / log(ratio));   // 45
    float sched[64];
    int cnt = 0;
    for (int k = 0; k <= n; k++) {
        double v = eps0 * pow(ratio, (double)k);
        if (v < epsf) v = epsf;
        sched[cnt++] = (float)v;
    }
    sched[cnt++] = (float)epsf;                          // cnt = 47

    for (int k = 0; k < cnt; k++)
        k_step<<<7 * 64, 256>>>(k & 1, sched[k], 1, 0);

    // final differentiable update at eps_f (no averaging, write final arrays)
    k_step<<<7 * 64, 256>>>(cnt & 1, (float)epsf, 0, 1);

    k_reduce<<<1, 256>>>(out);
}